// round 15
// baseline (speedup 1.0000x reference)
#include <cuda_runtime.h>
#include <cuda_fp16.h>
#include <math.h>
#include <float.h>
#include <stdint.h>

#define B_SZ   32
#define NHEADS 8
#define DHEAD  64
#define C_FMAP 512
#define NPIX   1024
#define NCTX   256
#define CCTX   768
#define DIMI   512   // NHEADS*DHEAD
#define BPG    8     // batches per group (4 groups, alternating 2 streams)

// ============================ scratch globals ============================
__device__ __half g_wq  [DIMI * C_FMAP];
__device__ __half g_wkv [2 * DIMI * CCTX];
__device__ __half g_wout[C_FMAP * DIMI];
__device__ __half g_fmapT[B_SZ * NPIX * C_FMAP];          // [b][p][c]
__device__ __half g_ctx  [B_SZ * NCTX * CCTX];            // [b][n][c]
__device__ __half g_qh [B_SZ * NHEADS * NPIX * DHEAD];    // [b][h][p][d]
__device__ __half g_kh [B_SZ * NHEADS * NCTX * DHEAD];    // [b][h][n][d]
__device__ __half g_vh [B_SZ * NHEADS * DHEAD * NCTX];    // [b][h][d][n]
__device__ __half g_att[B_SZ * NPIX * DIMI];              // [b][p][c]

// ============================ helpers ============================
__device__ __forceinline__ uint32_t smem_u32(const void* p) {
    uint32_t a;
    asm("{ .reg .u64 t; cvta.to.shared.u64 t, %1; cvt.u32.u64 %0, t; }" : "=r"(a) : "l"(p));
    return a;
}
__device__ __forceinline__ void ldsm4(uint32_t& r0, uint32_t& r1, uint32_t& r2, uint32_t& r3,
                                      uint32_t addr) {
    asm volatile("ldmatrix.sync.aligned.m8n8.x4.shared.b16 {%0,%1,%2,%3}, [%4];"
                 : "=r"(r0), "=r"(r1), "=r"(r2), "=r"(r3) : "r"(addr));
}
__device__ __forceinline__ void mma16816(float* c, const uint32_t* a, const uint32_t* b) {
    asm volatile("mma.sync.aligned.m16n8k16.row.col.f32.f16.f16.f32 "
                 "{%0,%1,%2,%3}, {%4,%5,%6,%7}, {%8,%9}, {%0,%1,%2,%3};"
                 : "+f"(c[0]), "+f"(c[1]), "+f"(c[2]), "+f"(c[3])
                 : "r"(a[0]), "r"(a[1]), "r"(a[2]), "r"(a[3]), "r"(b[0]), "r"(b[1]));
}
__device__ __forceinline__ void cpa16(uint32_t dst, const void* src) {
    asm volatile("cp.async.cg.shared.global [%0], [%1], 16;" :: "r"(dst), "l"(src));
}
#define CP_COMMIT() asm volatile("cp.async.commit_group;" ::: "memory")
#define CP_WAIT1()  asm volatile("cp.async.wait_group 1;" ::: "memory")
#define CP_WAIT0()  asm volatile("cp.async.wait_group 0;" ::: "memory")
__device__ __forceinline__ uint32_t h2pack(float lo, float hi) {
    __half2 h = __floats2half2_rn(lo, hi);
    return *(uint32_t*)&h;
}

// ============================ fused norm+prep kernels ============================

#define FF_SMEM (512 * 33 * 4 + 16 * 32 * 4 + 32 * 4)
__global__ void __launch_bounds__(512) fuse_fmap(const float* __restrict__ fmap,
                                                 const float* __restrict__ gamma) {
    extern __shared__ float fs[];
    float* t     = fs;                  // [512][33]
    float* red   = fs + 512 * 33;       // [16][32]
    float* scale = red + 16 * 32;       // [32]
    const int b = blockIdx.z, p0 = blockIdx.x * 32;
    const int tid = threadIdx.x;

    const float* src = fmap + (size_t)b * C_FMAP * NPIX + p0;
    #pragma unroll
    for (int it = 0; it < 32; it++) {
        int i = it * 512 + tid;
        int c = i >> 5, pi = i & 31;
        t[c * 33 + pi] = src[(size_t)c * NPIX + pi];
    }
    __syncthreads();

    {
        int p = tid & 31, sub = tid >> 5;
        float ss = 0.f;
        #pragma unroll
        for (int j = 0; j < 32; j++) {
            float v = t[(sub + 16 * j) * 33 + p];
            ss += v * v;
        }
        red[sub * 32 + p] = ss;
    }
    __syncthreads();
    if (tid < 32) {
        float ss = 0.f;
        #pragma unroll
        for (int s = 0; s < 16; s++) ss += red[s * 32 + tid];
        scale[tid] = 22.627416997969522f / fmaxf(sqrtf(ss), 1e-12f);
    }
    __syncthreads();

    #pragma unroll
    for (int it = 0; it < 32; it++) {
        int i = it * 512 + tid;
        int p = i >> 9, c = i & 511;
        float v = t[c * 33 + p] * scale[p] * __ldg(&gamma[c]);
        g_fmapT[((size_t)b * NPIX + p0 + p) * C_FMAP + c] = __float2half(v);
    }
}

__global__ void __launch_bounds__(256) fuse_ctx(const float* __restrict__ ctx,
                                                const float* __restrict__ gamma) {
    __shared__ float wred[8];
    __shared__ float sc;
    const int b = blockIdx.z, n = blockIdx.y;
    const int tid = threadIdx.x, lane = tid & 31, w = tid >> 5;
    size_t base = ((size_t)b * NCTX + n) * CCTX;
    const float* row = ctx + base;

    float v[3];
    float ss = 0.f;
    #pragma unroll
    for (int j = 0; j < 3; j++) {
        v[j] = row[j * 256 + tid];
        ss += v[j] * v[j];
    }
    #pragma unroll
    for (int o = 16; o; o >>= 1) ss += __shfl_xor_sync(0xffffffffu, ss, o);
    if (lane == 0) wred[w] = ss;
    __syncthreads();
    if (tid == 0) {
        float s = 0.f;
        #pragma unroll
        for (int i = 0; i < 8; i++) s += wred[i];
        sc = 27.712812921102035f / fmaxf(sqrtf(s), 1e-12f);
    }
    __syncthreads();
    float s = sc;
    #pragma unroll
    for (int j = 0; j < 3; j++) {
        int c = j * 256 + tid;
        g_ctx[base + c] = __float2half(v[j] * s * __ldg(&gamma[c]));
    }
}

#define NWQ  (DIMI * C_FMAP)
#define NWKV (2 * DIMI * CCTX)
#define NWO  (C_FMAP * DIMI)
__global__ void cvt_all(const float* __restrict__ wq, const float* __restrict__ wkv,
                        const float* __restrict__ wout) {
    int i = blockIdx.x * blockDim.x + threadIdx.x;
    if (i < NWQ) g_wq[i] = __float2half(wq[i]);
    else if (i < NWQ + NWKV) g_wkv[i - NWQ] = __float2half(wkv[i - NWQ]);
    else if (i < NWQ + NWKV + NWO) g_wout[i - NWQ - NWKV] = __float2half(wout[i - NWQ - NWKV]);
}

// ============================ fp16 mma GEMM body (BK=64, 2-stage, R10 config) ============================
// CTA 128x128, BK=64, 8 warps (4M x 2N) of 32x64, 256 threads, 2 CTAs/SM.

#define APITCH    144
#define HALF_STG  18432              // 128 * 144
#define STG_BYTES (2 * HALF_STG)
#define GMM_SMEM  (2 * STG_BYTES)    // 73728

template <int MODE>
__device__ __forceinline__ void gemm_body(
    const __half* __restrict__ aSrc, const __half* __restrict__ bSrc,
    int K, int m0, int n0, int b, float* __restrict__ outp, char* dsm) {
    const uint32_t smb = smem_u32(dsm);
    const int tid = threadIdx.x, lane = tid & 31, wid = tid >> 5;

    const int wm = (wid >> 1) * 32, wn = (wid & 1) * 64;
    const int rA = (lane & 7) + ((lane >> 3) & 1) * 8;
    const int kA = ((lane >> 4) & 1) * 8;
    const int nB = ((lane >> 4) & 1) * 8 + (lane & 7);
    const int kB = ((lane >> 3) & 1) * 8;

    float c[2][8][4];
    #pragma unroll
    for (int i = 0; i < 2; i++)
        #pragma unroll
        for (int j = 0; j < 8; j++)
            #pragma unroll
            for (int e = 0; e < 4; e++) c[i][j][e] = 0.f;

    const int nk = K >> 6;

    auto load_chunk = [&](int stage, int k0) {
        uint32_t base = smb + stage * STG_BYTES;
        #pragma unroll
        for (int it = 0; it < 4; it++) {
            int i = it * 256 + tid;
            int row = i >> 3, q = i & 7;
            cpa16(base + row * APITCH + q * 16, aSrc + (size_t)(m0 + row) * K + k0 + q * 8);
        }
        #pragma unroll
        for (int it = 0; it < 4; it++) {
            int i = it * 256 + tid;
            int row = i >> 3, q = i & 7;
            cpa16(base + HALF_STG + row * APITCH + q * 16,
                  bSrc + (size_t)(n0 + row) * K + k0 + q * 8);
        }
    };

    load_chunk(0, 0);
    CP_COMMIT();

    for (int ch = 0; ch < nk; ch++) {
        if (ch + 1 < nk) { load_chunk((ch + 1) & 1, (ch + 1) << 6); CP_COMMIT(); CP_WAIT1(); }
        else CP_WAIT0();
        __syncthreads();

        const uint32_t sAb = smb + (ch & 1) * STG_BYTES;
        const uint32_t sBb = sAb + HALF_STG;

        #pragma unroll
        for (int kk = 0; kk < 64; kk += 16) {
            uint32_t af[2][4], bf[8][2];
            #pragma unroll
            for (int mt = 0; mt < 2; mt++)
                ldsm4(af[mt][0], af[mt][1], af[mt][2], af[mt][3],
                      sAb + (wm + mt * 16 + rA) * APITCH + (kk + kA) * 2);
            #pragma unroll
            for (int pr = 0; pr < 4; pr++) {
                uint32_t t0, t1, t2, t3;
                ldsm4(t0, t1, t2, t3, sBb + (wn + pr * 16 + nB) * APITCH + (kk + kB) * 2);
                bf[pr * 2][0] = t0; bf[pr * 2][1] = t1;
                bf[pr * 2 + 1][0] = t2; bf[pr * 2 + 1][1] = t3;
            }
            #pragma unroll
            for (int mt = 0; mt < 2; mt++)
                #pragma unroll
                for (int nt = 0; nt < 8; nt++)
                    mma16816(c[mt][nt], af[mt], bf[nt]);
        }
        __syncthreads();
    }

    // epilogue
    const int gmb = m0 + wm + (lane >> 2);
    const int gnb = n0 + wn + (lane & 3) * 2;
    #pragma unroll
    for (int mt = 0; mt < 2; mt++) {
        #pragma unroll
        for (int nt = 0; nt < 8; nt++) {
            int gm0 = gmb + mt * 16;
            int gn  = gnb + nt * 8;
            float v0 = c[mt][nt][0], v1 = c[mt][nt][1];
            float v2 = c[mt][nt][2], v3 = c[mt][nt][3];
            if (MODE == 0) {
                int h = gn >> 6, d = gn & 63;
                __half* dst = g_qh + ((size_t)(b * NHEADS + h) * NPIX) * DHEAD + d;
                *(uint32_t*)(dst + (size_t)gm0 * DHEAD)       = h2pack(v0, v1);
                *(uint32_t*)(dst + (size_t)(gm0 + 8) * DHEAD) = h2pack(v2, v3);
            } else if (MODE == 1) {
                auto st = [&](int o, float x0, float x1) {
                    if (o < DIMI) {
                        __half* dst = g_kh + ((size_t)(b * NHEADS + (o >> 6)) * NCTX) * DHEAD + (o & 63);
                        dst[(size_t)gn * DHEAD]       = __float2half(x0);
                        dst[(size_t)(gn + 1) * DHEAD] = __float2half(x1);
                    } else {
                        int o2 = o - DIMI;
                        __half* dst = g_vh + ((size_t)(b * NHEADS + (o2 >> 6)) * DHEAD + (o2 & 63)) * NCTX;
                        *(uint32_t*)(dst + gn) = h2pack(x0, x1);
                    }
                };
                st(gm0, v0, v1);
                st(gm0 + 8, v2, v3);
            } else {
                float* dst = outp + ((size_t)b * C_FMAP) * NPIX + gn;
                *(float2*)(dst + (size_t)gm0 * NPIX)       = make_float2(v0, v1);
                *(float2*)(dst + (size_t)(gm0 + 8) * NPIX) = make_float2(v2, v3);
            }
        }
    }
}

// Merged Q + KV projection for one batch group: grid (6, 8, BPG).
__global__ void __launch_bounds__(256, 2)
gemm_qkv(const __half* __restrict__ fT, const __half* __restrict__ wq,
         const __half* __restrict__ wkv, const __half* __restrict__ cx, int b0) {
    extern __shared__ char dsm[];
    const int b = b0 + blockIdx.z;
    if (blockIdx.x < 4) {
        gemm_body<0>(fT + (size_t)b * NPIX * C_FMAP, wq,
                     C_FMAP, blockIdx.y * 128, blockIdx.x * 128, b, nullptr, dsm);
    } else {
        int nx = blockIdx.x - 4;
        gemm_body<1>(wkv, cx + (size_t)b * NCTX * CCTX,
                     CCTX, blockIdx.y * 128, nx * 128, b, nullptr, dsm);
    }
}

__global__ void __launch_bounds__(256, 2)
gemm_out(const __half* __restrict__ wout, const __half* __restrict__ at,
         float* __restrict__ outp, int b0) {
    extern __shared__ char dsm[];
    const int b = b0 + blockIdx.z;
    gemm_body<2>(wout, at + (size_t)b * NPIX * DIMI,
                 DIMI, blockIdx.y * 128, blockIdx.x * 128, b, outp, dsm);
}

// ============================ persistent attention (fp16 mma) ============================

#define AQ_BYTES (64 * 72 * 2)
#define AK_BYTES (256 * 72 * 2)
#define AV_BYTES (64 * 264 * 2)
#define APB_BYTES (64 * 64 * 4)
#define ATTN_SMEM (AQ_BYTES + AK_BYTES + AV_BYTES + APB_BYTES + 1024 + 512 + 512)

__global__ void __launch_bounds__(256, 2) attn_mma(const int* __restrict__ mask, int b0) {
    extern __shared__ char smraw[];
    __half* Qs = (__half*)smraw;
    __half* Ks = (__half*)(smraw + AQ_BYTES);
    __half* Vs = (__half*)(smraw + AQ_BYTES + AK_BYTES);
    float*  pairbuf = (float*)(smraw + AQ_BYTES + AK_BYTES + AV_BYTES);
    float*  mf = pairbuf + 64 * 64;
    float*  redmax = mf + 256;
    float*  redsum = redmax + 128;

    const int tid = threadIdx.x, lane = tid & 31, w = tid >> 5;
    const int rg = w >> 1, chh = w & 1;
    const int b = b0 + blockIdx.z, h = blockIdx.y;

    const uint4* qsrc = (const uint4*)(g_qh + ((size_t)(b * NHEADS + h) * NPIX) * DHEAD);
    const uint4* ksrc = (const uint4*)(g_kh + (size_t)(b * NHEADS + h) * NCTX * DHEAD);
    const uint4* vsrc = (const uint4*)(g_vh + (size_t)(b * NHEADS + h) * DHEAD * NCTX);

    for (int i = tid; i < 2048; i += 256) {
        int row = i >> 3, q = i & 7;
        *(uint4*)&Ks[row * 72 + q * 8] = ksrc[i];
    }
    for (int i = tid; i < 2048; i += 256) {
        int row = i >> 5, q = i & 31;
        *(uint4*)&Vs[row * 264 + q * 8] = vsrc[i];
    }
    mf[tid] = (mask[b * NCTX + tid] != 0) ? 1.0f : 0.0f;

    const uint32_t qb = smem_u32(Qs), kb = smem_u32(Ks), vb = smem_u32(Vs);
    const int rA = (lane & 7) + ((lane >> 3) & 1) * 8;
    const int kA = ((lane >> 4) & 1) * 8;
    const int nB = ((lane >> 4) & 1) * 8 + (lane & 7);
    const int kB = ((lane >> 3) & 1) * 8;
    const int r0 = rg * 16 + (lane >> 2);

    for (int pt = 0; pt < 16; pt++) {
        const int p0 = pt * 64;
        __syncthreads();
        for (int i = tid; i < 512; i += 256) {
            int row = i >> 3, q = i & 7;
            *(uint4*)&Qs[row * 72 + q * 8] = qsrc[pt * 512 + i];
        }
        __syncthreads();

        float c[16][4];
        #pragma unroll
        for (int j = 0; j < 16; j++)
            #pragma unroll
            for (int e = 0; e < 4; e++) c[j][e] = 0.f;

        #pragma unroll
        for (int kst = 0; kst < 4; kst++) {
            int kk = kst * 16;
            uint32_t a[4];
            ldsm4(a[0], a[1], a[2], a[3], qb + (rg * 16 + rA) * 144 + (kk + kA) * 2);
            #pragma unroll
            for (int g16 = 0; g16 < 8; g16++) {
                uint32_t t0, t1, t2, t3;
                ldsm4(t0, t1, t2, t3, kb + (chh * 128 + g16 * 16 + nB) * 144 + (kk + kB) * 2);
                uint32_t b0v[2] = {t0, t1}, b1v[2] = {t2, t3};
                mma16816(c[g16 * 2],     a, b0v);
                mma16816(c[g16 * 2 + 1], a, b1v);
            }
        }

        float m0 = -FLT_MAX, m1 = -FLT_MAX;
        #pragma unroll
        for (int j = 0; j < 16; j++) {
            c[j][0] *= 0.125f; c[j][1] *= 0.125f; c[j][2] *= 0.125f; c[j][3] *= 0.125f;
            m0 = fmaxf(m0, fmaxf(c[j][0], c[j][1]));
            m1 = fmaxf(m1, fmaxf(c[j][2], c[j][3]));
        }
        #pragma unroll
        for (int o = 1; o <= 2; o <<= 1) {
            m0 = fmaxf(m0, __shfl_xor_sync(0xffffffffu, m0, o));
            m1 = fmaxf(m1, __shfl_xor_sync(0xffffffffu, m1, o));
        }
        if ((lane & 3) == 0) {
            redmax[r0 * 2 + chh]       = m0;
            redmax[(r0 + 8) * 2 + chh] = m1;
        }
        __syncthreads();
        float M0 = fmaxf(redmax[r0 * 2], redmax[r0 * 2 + 1]);
        float M1 = fmaxf(redmax[(r0 + 8) * 2], redmax[(r0 + 8) * 2 + 1]);

        float s0 = 0.f, s1 = 0.f;
        #pragma unroll
        for (int j = 0; j < 16; j++) {
            int col = chh * 128 + j * 8 + (lane & 3) * 2;
            float mA = mf[col], mB = mf[col + 1];
            float e0 = __expf(c[j][0] - M0) * mA;
            float e1 = __expf(c[j][1] - M0) * mB;
            float e2 = __expf(c[j][2] - M1) * mA;
            float e3 = __expf(c[j][3] - M1) * mB;
            c[j][0] = e0; c[j][1] = e1; c[j][2] = e2; c[j][3] = e3;
            s0 += e0 + e1; s1 += e2 + e3;
        }
        #pragma unroll
        for (int o = 1; o <= 2; o <<= 1) {
            s0 += __shfl_xor_sync(0xffffffffu, s0, o);
            s1 += __shfl_xor_sync(0xffffffffu, s1, o);
        }
        if ((lane & 3) == 0) {
            redsum[r0 * 2 + chh]       = s0;
            redsum[(r0 + 8) * 2 + chh] = s1;
        }
        __syncthreads();
        float rs0 = 1.f / (redsum[r0 * 2] + redsum[r0 * 2 + 1]);
        float rs1 = 1.f / (redsum[(r0 + 8) * 2] + redsum[(r0 + 8) * 2 + 1]);

        uint32_t pf[32];
        #pragma unroll
        for (int t = 0; t < 8; t++) {
            int j = t * 2;
            pf[t * 4 + 0] = h2pack(c[j][0], c[j][1]);
            pf[t * 4 + 1] = h2pack(c[j][2], c[j][3]);
            pf[t * 4 + 2] = h2pack(c[j + 1][0], c[j + 1][1]);
            pf[t * 4 + 3] = h2pack(c[j + 1][2], c[j + 1][3]);
        }

        float o2[8][4];
        #pragma unroll
        for (int nt = 0; nt < 8; nt++)
            #pragma unroll
            for (int e = 0; e < 4; e++) o2[nt][e] = 0.f;

        #pragma unroll
        for (int t = 0; t < 8; t++) {
            #pragma unroll
            for (int dg = 0; dg < 4; dg++) {
                uint32_t t0, t1, t2, t3;
                ldsm4(t0, t1, t2, t3, vb + (dg * 16 + nB) * 528 + (chh * 128 + t * 16 + kB) * 2);
                uint32_t b0v[2] = {t0, t1}, b1v[2] = {t2, t3};
                mma16816(o2[dg * 2],     &pf[t * 4], b0v);
                mma16816(o2[dg * 2 + 1], &pf[t * 4], b1v);
            }
        }

        if (chh == 0) {
            #pragma unroll
            for (int nt = 0; nt < 8; nt++) {
                int d = nt * 8 + (lane & 3) * 2;
                *(float2*)&pairbuf[r0 * 64 + d]       = make_float2(o2[nt][0], o2[nt][1]);
                *(float2*)&pairbuf[(r0 + 8) * 64 + d] = make_float2(o2[nt][2], o2[nt][3]);
            }
        }
        __syncthreads();
        if (chh == 1) {
            #pragma unroll
            for (int nt = 0; nt < 8; nt++) {
                int d = nt * 8 + (lane & 3) * 2;
                float2 pa = *(float2*)&pairbuf[r0 * 64 + d];
                float2 pb = *(float2*)&pairbuf[(r0 + 8) * 64 + d];
                float v0 = (o2[nt][0] + pa.x) * rs0, v1 = (o2[nt][1] + pa.y) * rs0;
                float v2 = (o2[nt][2] + pb.x) * rs1, v3 = (o2[nt][3] + pb.y) * rs1;
                __half* dst = g_att + ((size_t)b * NPIX) * DIMI + h * 64 + d;
                *(uint32_t*)(dst + (size_t)(p0 + r0) * DIMI)     = h2pack(v0, v1);
                *(uint32_t*)(dst + (size_t)(p0 + r0 + 8) * DIMI) = h2pack(v2, v3);
            }
        }
    }
}

// ============================ launch ============================

extern "C" void kernel_launch(void* const* d_in, const int* in_sizes, int n_in,
                              void* d_out, int out_size) {
    const float* fmap       = (const float*)d_in[0];
    const float* context    = (const float*)d_in[1];
    const int*   mask       = (const int*)d_in[2];
    const float* gamma_fmap = (const float*)d_in[3];
    const float* gamma_ctx  = (const float*)d_in[4];
    const float* Wq         = (const float*)d_in[5];
    const float* Wkv        = (const float*)d_in[6];
    const float* Wout       = (const float*)d_in[7];
    float*       out        = (float*)d_out;

    (void)in_sizes; (void)n_in; (void)out_size;

    // Proven-legal resource set: 2 streams + 3 events (R11/R13 footprint).
    static cudaStream_t sA = nullptr, sB = nullptr;
    static cudaEvent_t evRoot = nullptr, evA = nullptr, evB = nullptr;
    if (!sA) {
        cudaStreamCreateWithFlags(&sA, cudaStreamNonBlocking);
        cudaStreamCreateWithFlags(&sB, cudaStreamNonBlocking);
        cudaEventCreateWithFlags(&evRoot, cudaEventDisableTiming);
        cudaEventCreateWithFlags(&evA, cudaEventDisableTiming);
        cudaEventCreateWithFlags(&evB, cudaEventDisableTiming);
    }

    cudaFuncSetAttribute(attn_mma, cudaFuncAttributeMaxDynamicSharedMemorySize, ATTN_SMEM);
    cudaFuncSetAttribute(fuse_fmap, cudaFuncAttributeMaxDynamicSharedMemorySize, FF_SMEM);
    cudaFuncSetAttribute(gemm_qkv, cudaFuncAttributeMaxDynamicSharedMemorySize, GMM_SMEM);
    cudaFuncSetAttribute(gemm_out, cudaFuncAttributeMaxDynamicSharedMemorySize, GMM_SMEM);

    __half *fT, *cx, *at, *wq, *wkv, *wout;
    cudaGetSymbolAddress((void**)&fT, g_fmapT);
    cudaGetSymbolAddress((void**)&cx, g_ctx);
    cudaGetSymbolAddress((void**)&at, g_att);
    cudaGetSymbolAddress((void**)&wq,  g_wq);
    cudaGetSymbolAddress((void**)&wkv, g_wkv);
    cudaGetSymbolAddress((void**)&wout, g_wout);

    // ---- fork preps ----
    cudaEventRecord(evRoot, 0);
    cudaStreamWaitEvent(sA, evRoot, 0);
    cudaStreamWaitEvent(sB, evRoot, 0);

    cvt_all<<<(NWQ + NWKV + NWO + 255) / 256, 256>>>(Wq, Wkv, Wout);
    fuse_fmap<<<dim3(NPIX / 32, 1, B_SZ), 512, FF_SMEM, sA>>>(fmap, gamma_fmap);
    fuse_ctx<<<dim3(1, NCTX, B_SZ), 256, 0, sB>>>(context, gamma_ctx);

    cudaEventRecord(evA, sA);
    cudaEventRecord(evB, sB);
    cudaStreamWaitEvent(0, evA, 0);
    cudaStreamWaitEvent(0, evB, 0);
    cudaEventRecord(evRoot, 0);          // prep-done marker
    cudaStreamWaitEvent(sB, evRoot, 0);

    // ---- 4 groups of 8, alternating across 2 streams (no cross-stream deps,
    //      R13-style simultaneous issue; finer interleave granularity) ----
    for (int g = 0; g < 4; g++) {
        int b0 = g * BPG;
        cudaStream_t st = (g & 1) ? sB : (cudaStream_t)0;
        gemm_qkv<<<dim3(6, 8, BPG), 256, GMM_SMEM, st>>>(fT, wq, wkv, cx, b0);
        attn_mma<<<dim3(1, NHEADS, BPG), 256, ATTN_SMEM, st>>>(mask, b0);
        gemm_out<<<dim3(NPIX / 128, C_FMAP / 128, BPG), 256, GMM_SMEM, st>>>(wout, at, out, b0);
    }

    cudaEventRecord(evB, sB);            // join stream B
    cudaStreamWaitEvent(0, evB, 0);
}

// round 16
// speedup vs baseline: 1.8578x; 1.8578x over previous
#include <cuda_runtime.h>
#include <cuda_fp16.h>
#include <math.h>
#include <float.h>
#include <stdint.h>

#define B_SZ   32
#define NHEADS 8
#define DHEAD  64
#define C_FMAP 512
#define NPIX   1024
#define NCTX   256
#define CCTX   768
#define DIMI   512   // NHEADS*DHEAD
#define BPG    16    // batches per group (2 groups)

// ============================ scratch globals ============================
__device__ __half g_wq  [DIMI * C_FMAP];
__device__ __half g_wkv [2 * DIMI * CCTX];
__device__ __half g_wout[C_FMAP * DIMI];
__device__ __half g_fmapT[B_SZ * NPIX * C_FMAP];          // [b][p][c]
__device__ __half g_ctx  [B_SZ * NCTX * CCTX];            // [b][n][c]
__device__ __half g_qh [B_SZ * NHEADS * NPIX * DHEAD];    // [b][h][p][d]
__device__ __half g_kh [B_SZ * NHEADS * NCTX * DHEAD];    // [b][h][n][d]
__device__ __half g_vh [B_SZ * NHEADS * DHEAD * NCTX];    // [b][h][d][n]
__device__ __half g_att[B_SZ * NPIX * DIMI];              // [b][p][c]

// ============================ helpers ============================
__device__ __forceinline__ uint32_t smem_u32(const void* p) {
    uint32_t a;
    asm("{ .reg .u64 t; cvta.to.shared.u64 t, %1; cvt.u32.u64 %0, t; }" : "=r"(a) : "l"(p));
    return a;
}
__device__ __forceinline__ void ldsm4(uint32_t& r0, uint32_t& r1, uint32_t& r2, uint32_t& r3,
                                      uint32_t addr) {
    asm volatile("ldmatrix.sync.aligned.m8n8.x4.shared.b16 {%0,%1,%2,%3}, [%4];"
                 : "=r"(r0), "=r"(r1), "=r"(r2), "=r"(r3) : "r"(addr));
}
__device__ __forceinline__ void mma16816(float* c, const uint32_t* a, const uint32_t* b) {
    asm volatile("mma.sync.aligned.m16n8k16.row.col.f32.f16.f16.f32 "
                 "{%0,%1,%2,%3}, {%4,%5,%6,%7}, {%8,%9}, {%0,%1,%2,%3};"
                 : "+f"(c[0]), "+f"(c[1]), "+f"(c[2]), "+f"(c[3])
                 : "r"(a[0]), "r"(a[1]), "r"(a[2]), "r"(a[3]), "r"(b[0]), "r"(b[1]));
}
__device__ __forceinline__ void cpa16(uint32_t dst, const void* src) {
    asm volatile("cp.async.cg.shared.global [%0], [%1], 16;" :: "r"(dst), "l"(src));
}
#define CP_COMMIT() asm volatile("cp.async.commit_group;" ::: "memory")
#define CP_WAIT1()  asm volatile("cp.async.wait_group 1;" ::: "memory")
#define CP_WAIT0()  asm volatile("cp.async.wait_group 0;" ::: "memory")
__device__ __forceinline__ uint32_t h2pack(float lo, float hi) {
    __half2 h = __floats2half2_rn(lo, hi);
    return *(uint32_t*)&h;
}

// ============================ fused norm+prep kernels ============================

#define FF_SMEM (512 * 33 * 4 + 16 * 32 * 4 + 32 * 4)
__global__ void __launch_bounds__(512) fuse_fmap(const float* __restrict__ fmap,
                                                 const float* __restrict__ gamma) {
    extern __shared__ float fs[];
    float* t     = fs;                  // [512][33]
    float* red   = fs + 512 * 33;       // [16][32]
    float* scale = red + 16 * 32;       // [32]
    const int b = blockIdx.z, p0 = blockIdx.x * 32;
    const int tid = threadIdx.x;

    const float* src = fmap + (size_t)b * C_FMAP * NPIX + p0;
    #pragma unroll
    for (int it = 0; it < 32; it++) {
        int i = it * 512 + tid;
        int c = i >> 5, pi = i & 31;
        t[c * 33 + pi] = src[(size_t)c * NPIX + pi];
    }
    __syncthreads();

    {
        int p = tid & 31, sub = tid >> 5;
        float ss = 0.f;
        #pragma unroll
        for (int j = 0; j < 32; j++) {
            float v = t[(sub + 16 * j) * 33 + p];
            ss += v * v;
        }
        red[sub * 32 + p] = ss;
    }
    __syncthreads();
    if (tid < 32) {
        float ss = 0.f;
        #pragma unroll
        for (int s = 0; s < 16; s++) ss += red[s * 32 + tid];
        scale[tid] = 22.627416997969522f / fmaxf(sqrtf(ss), 1e-12f);
    }
    __syncthreads();

    #pragma unroll
    for (int it = 0; it < 32; it++) {
        int i = it * 512 + tid;
        int p = i >> 9, c = i & 511;
        float v = t[c * 33 + p] * scale[p] * __ldg(&gamma[c]);
        g_fmapT[((size_t)b * NPIX + p0 + p) * C_FMAP + c] = __float2half(v);
    }
}

__global__ void __launch_bounds__(256) fuse_ctx(const float* __restrict__ ctx,
                                                const float* __restrict__ gamma) {
    __shared__ float wred[8];
    __shared__ float sc;
    const int b = blockIdx.z, n = blockIdx.y;
    const int tid = threadIdx.x, lane = tid & 31, w = tid >> 5;
    size_t base = ((size_t)b * NCTX + n) * CCTX;
    const float* row = ctx + base;

    float v[3];
    float ss = 0.f;
    #pragma unroll
    for (int j = 0; j < 3; j++) {
        v[j] = row[j * 256 + tid];
        ss += v[j] * v[j];
    }
    #pragma unroll
    for (int o = 16; o; o >>= 1) ss += __shfl_xor_sync(0xffffffffu, ss, o);
    if (lane == 0) wred[w] = ss;
    __syncthreads();
    if (tid == 0) {
        float s = 0.f;
        #pragma unroll
        for (int i = 0; i < 8; i++) s += wred[i];
        sc = 27.712812921102035f / fmaxf(sqrtf(s), 1e-12f);
    }
    __syncthreads();
    float s = sc;
    #pragma unroll
    for (int j = 0; j < 3; j++) {
        int c = j * 256 + tid;
        g_ctx[base + c] = __float2half(v[j] * s * __ldg(&gamma[c]));
    }
}

#define NWQ  (DIMI * C_FMAP)
#define NWKV (2 * DIMI * CCTX)
#define NWO  (C_FMAP * DIMI)
__global__ void cvt_all(const float* __restrict__ wq, const float* __restrict__ wkv,
                        const float* __restrict__ wout) {
    int i = blockIdx.x * blockDim.x + threadIdx.x;
    if (i < NWQ) g_wq[i] = __float2half(wq[i]);
    else if (i < NWQ + NWKV) g_wkv[i - NWQ] = __float2half(wkv[i - NWQ]);
    else if (i < NWQ + NWKV + NWO) g_wout[i - NWQ - NWKV] = __float2half(wout[i - NWQ - NWKV]);
}

// ============================ fp16 mma GEMM body (BK=64, 2-stage, R10 config) ============================
// CTA 128x128, BK=64, 8 warps (4M x 2N) of 32x64, 256 threads, 2 CTAs/SM.

#define APITCH    144
#define HALF_STG  18432              // 128 * 144
#define STG_BYTES (2 * HALF_STG)
#define GMM_SMEM  (2 * STG_BYTES)    // 73728

template <int MODE>
__device__ __forceinline__ void gemm_body(
    const __half* __restrict__ aSrc, const __half* __restrict__ bSrc,
    int K, int m0, int n0, int b, float* __restrict__ outp, char* dsm) {
    const uint32_t smb = smem_u32(dsm);
    const int tid = threadIdx.x, lane = tid & 31, wid = tid >> 5;

    const int wm = (wid >> 1) * 32, wn = (wid & 1) * 64;
    const int rA = (lane & 7) + ((lane >> 3) & 1) * 8;
    const int kA = ((lane >> 4) & 1) * 8;
    const int nB = ((lane >> 4) & 1) * 8 + (lane & 7);
    const int kB = ((lane >> 3) & 1) * 8;

    float c[2][8][4];
    #pragma unroll
    for (int i = 0; i < 2; i++)
        #pragma unroll
        for (int j = 0; j < 8; j++)
            #pragma unroll
            for (int e = 0; e < 4; e++) c[i][j][e] = 0.f;

    const int nk = K >> 6;

    auto load_chunk = [&](int stage, int k0) {
        uint32_t base = smb + stage * STG_BYTES;
        #pragma unroll
        for (int it = 0; it < 4; it++) {
            int i = it * 256 + tid;
            int row = i >> 3, q = i & 7;
            cpa16(base + row * APITCH + q * 16, aSrc + (size_t)(m0 + row) * K + k0 + q * 8);
        }
        #pragma unroll
        for (int it = 0; it < 4; it++) {
            int i = it * 256 + tid;
            int row = i >> 3, q = i & 7;
            cpa16(base + HALF_STG + row * APITCH + q * 16,
                  bSrc + (size_t)(n0 + row) * K + k0 + q * 8);
        }
    };

    load_chunk(0, 0);
    CP_COMMIT();

    for (int ch = 0; ch < nk; ch++) {
        if (ch + 1 < nk) { load_chunk((ch + 1) & 1, (ch + 1) << 6); CP_COMMIT(); CP_WAIT1(); }
        else CP_WAIT0();
        __syncthreads();

        const uint32_t sAb = smb + (ch & 1) * STG_BYTES;
        const uint32_t sBb = sAb + HALF_STG;

        #pragma unroll
        for (int kk = 0; kk < 64; kk += 16) {
            uint32_t af[2][4], bf[8][2];
            #pragma unroll
            for (int mt = 0; mt < 2; mt++)
                ldsm4(af[mt][0], af[mt][1], af[mt][2], af[mt][3],
                      sAb + (wm + mt * 16 + rA) * APITCH + (kk + kA) * 2);
            #pragma unroll
            for (int pr = 0; pr < 4; pr++) {
                uint32_t t0, t1, t2, t3;
                ldsm4(t0, t1, t2, t3, sBb + (wn + pr * 16 + nB) * APITCH + (kk + kB) * 2);
                bf[pr * 2][0] = t0; bf[pr * 2][1] = t1;
                bf[pr * 2 + 1][0] = t2; bf[pr * 2 + 1][1] = t3;
            }
            #pragma unroll
            for (int mt = 0; mt < 2; mt++)
                #pragma unroll
                for (int nt = 0; nt < 8; nt++)
                    mma16816(c[mt][nt], af[mt], bf[nt]);
        }
        __syncthreads();
    }

    // epilogue
    const int gmb = m0 + wm + (lane >> 2);
    const int gnb = n0 + wn + (lane & 3) * 2;
    #pragma unroll
    for (int mt = 0; mt < 2; mt++) {
        #pragma unroll
        for (int nt = 0; nt < 8; nt++) {
            int gm0 = gmb + mt * 16;
            int gn  = gnb + nt * 8;
            float v0 = c[mt][nt][0], v1 = c[mt][nt][1];
            float v2 = c[mt][nt][2], v3 = c[mt][nt][3];
            if (MODE == 0) {
                int h = gn >> 6, d = gn & 63;
                __half* dst = g_qh + ((size_t)(b * NHEADS + h) * NPIX) * DHEAD + d;
                *(uint32_t*)(dst + (size_t)gm0 * DHEAD)       = h2pack(v0, v1);
                *(uint32_t*)(dst + (size_t)(gm0 + 8) * DHEAD) = h2pack(v2, v3);
            } else if (MODE == 1) {
                auto st = [&](int o, float x0, float x1) {
                    if (o < DIMI) {
                        __half* dst = g_kh + ((size_t)(b * NHEADS + (o >> 6)) * NCTX) * DHEAD + (o & 63);
                        dst[(size_t)gn * DHEAD]       = __float2half(x0);
                        dst[(size_t)(gn + 1) * DHEAD] = __float2half(x1);
                    } else {
                        int o2 = o - DIMI;
                        __half* dst = g_vh + ((size_t)(b * NHEADS + (o2 >> 6)) * DHEAD + (o2 & 63)) * NCTX;
                        *(uint32_t*)(dst + gn) = h2pack(x0, x1);
                    }
                };
                st(gm0, v0, v1);
                st(gm0 + 8, v2, v3);
            } else {
                float* dst = outp + ((size_t)b * C_FMAP) * NPIX + gn;
                *(float2*)(dst + (size_t)gm0 * NPIX)       = make_float2(v0, v1);
                *(float2*)(dst + (size_t)(gm0 + 8) * NPIX) = make_float2(v2, v3);
            }
        }
    }
}

// Merged Q + KV projection for one batch group: grid (6, 8, BPG).
__global__ void __launch_bounds__(256, 2)
gemm_qkv(const __half* __restrict__ fT, const __half* __restrict__ wq,
         const __half* __restrict__ wkv, const __half* __restrict__ cx, int b0) {
    extern __shared__ char dsm[];
    const int b = b0 + blockIdx.z;
    if (blockIdx.x < 4) {
        gemm_body<0>(fT + (size_t)b * NPIX * C_FMAP, wq,
                     C_FMAP, blockIdx.y * 128, blockIdx.x * 128, b, nullptr, dsm);
    } else {
        int nx = blockIdx.x - 4;
        gemm_body<1>(wkv, cx + (size_t)b * NCTX * CCTX,
                     CCTX, blockIdx.y * 128, nx * 128, b, nullptr, dsm);
    }
}

__global__ void __launch_bounds__(256, 2)
gemm_out(const __half* __restrict__ wout, const __half* __restrict__ at,
         float* __restrict__ outp, int b0) {
    extern __shared__ char dsm[];
    const int b = b0 + blockIdx.z;
    gemm_body<2>(wout, at + (size_t)b * NPIX * DIMI,
                 DIMI, blockIdx.y * 128, blockIdx.x * 128, b, outp, dsm);
}

// ============================ persistent attention (fp16 mma) ============================

#define AQ_BYTES (64 * 72 * 2)
#define AK_BYTES (256 * 72 * 2)
#define AV_BYTES (64 * 264 * 2)
#define APB_BYTES (64 * 64 * 4)
#define ATTN_SMEM (AQ_BYTES + AK_BYTES + AV_BYTES + APB_BYTES + 1024 + 512 + 512)

__global__ void __launch_bounds__(256, 2) attn_mma(const int* __restrict__ mask, int b0) {
    extern __shared__ char smraw[];
    __half* Qs = (__half*)smraw;
    __half* Ks = (__half*)(smraw + AQ_BYTES);
    __half* Vs = (__half*)(smraw + AQ_BYTES + AK_BYTES);
    float*  pairbuf = (float*)(smraw + AQ_BYTES + AK_BYTES + AV_BYTES);
    float*  mf = pairbuf + 64 * 64;
    float*  redmax = mf + 256;
    float*  redsum = redmax + 128;

    const int tid = threadIdx.x, lane = tid & 31, w = tid >> 5;
    const int rg = w >> 1, chh = w & 1;
    const int b = b0 + blockIdx.z, h = blockIdx.y;

    const uint4* qsrc = (const uint4*)(g_qh + ((size_t)(b * NHEADS + h) * NPIX) * DHEAD);
    const uint4* ksrc = (const uint4*)(g_kh + (size_t)(b * NHEADS + h) * NCTX * DHEAD);
    const uint4* vsrc = (const uint4*)(g_vh + (size_t)(b * NHEADS + h) * DHEAD * NCTX);

    for (int i = tid; i < 2048; i += 256) {
        int row = i >> 3, q = i & 7;
        *(uint4*)&Ks[row * 72 + q * 8] = ksrc[i];
    }
    for (int i = tid; i < 2048; i += 256) {
        int row = i >> 5, q = i & 31;
        *(uint4*)&Vs[row * 264 + q * 8] = vsrc[i];
    }
    mf[tid] = (mask[b * NCTX + tid] != 0) ? 1.0f : 0.0f;

    const uint32_t qb = smem_u32(Qs), kb = smem_u32(Ks), vb = smem_u32(Vs);
    const int rA = (lane & 7) + ((lane >> 3) & 1) * 8;
    const int kA = ((lane >> 4) & 1) * 8;
    const int nB = ((lane >> 4) & 1) * 8 + (lane & 7);
    const int kB = ((lane >> 3) & 1) * 8;
    const int r0 = rg * 16 + (lane >> 2);

    for (int pt = 0; pt < 16; pt++) {
        const int p0 = pt * 64;
        __syncthreads();
        for (int i = tid; i < 512; i += 256) {
            int row = i >> 3, q = i & 7;
            *(uint4*)&Qs[row * 72 + q * 8] = qsrc[pt * 512 + i];
        }
        __syncthreads();

        float c[16][4];
        #pragma unroll
        for (int j = 0; j < 16; j++)
            #pragma unroll
            for (int e = 0; e < 4; e++) c[j][e] = 0.f;

        #pragma unroll
        for (int kst = 0; kst < 4; kst++) {
            int kk = kst * 16;
            uint32_t a[4];
            ldsm4(a[0], a[1], a[2], a[3], qb + (rg * 16 + rA) * 144 + (kk + kA) * 2);
            #pragma unroll
            for (int g16 = 0; g16 < 8; g16++) {
                uint32_t t0, t1, t2, t3;
                ldsm4(t0, t1, t2, t3, kb + (chh * 128 + g16 * 16 + nB) * 144 + (kk + kB) * 2);
                uint32_t b0v[2] = {t0, t1}, b1v[2] = {t2, t3};
                mma16816(c[g16 * 2],     a, b0v);
                mma16816(c[g16 * 2 + 1], a, b1v);
            }
        }

        float m0 = -FLT_MAX, m1 = -FLT_MAX;
        #pragma unroll
        for (int j = 0; j < 16; j++) {
            c[j][0] *= 0.125f; c[j][1] *= 0.125f; c[j][2] *= 0.125f; c[j][3] *= 0.125f;
            m0 = fmaxf(m0, fmaxf(c[j][0], c[j][1]));
            m1 = fmaxf(m1, fmaxf(c[j][2], c[j][3]));
        }
        #pragma unroll
        for (int o = 1; o <= 2; o <<= 1) {
            m0 = fmaxf(m0, __shfl_xor_sync(0xffffffffu, m0, o));
            m1 = fmaxf(m1, __shfl_xor_sync(0xffffffffu, m1, o));
        }
        if ((lane & 3) == 0) {
            redmax[r0 * 2 + chh]       = m0;
            redmax[(r0 + 8) * 2 + chh] = m1;
        }
        __syncthreads();
        float M0 = fmaxf(redmax[r0 * 2], redmax[r0 * 2 + 1]);
        float M1 = fmaxf(redmax[(r0 + 8) * 2], redmax[(r0 + 8) * 2 + 1]);

        float s0 = 0.f, s1 = 0.f;
        #pragma unroll
        for (int j = 0; j < 16; j++) {
            int col = chh * 128 + j * 8 + (lane & 3) * 2;
            float mA = mf[col], mB = mf[col + 1];
            float e0 = __expf(c[j][0] - M0) * mA;
            float e1 = __expf(c[j][1] - M0) * mB;
            float e2 = __expf(c[j][2] - M1) * mA;
            float e3 = __expf(c[j][3] - M1) * mB;
            c[j][0] = e0; c[j][1] = e1; c[j][2] = e2; c[j][3] = e3;
            s0 += e0 + e1; s1 += e2 + e3;
        }
        #pragma unroll
        for (int o = 1; o <= 2; o <<= 1) {
            s0 += __shfl_xor_sync(0xffffffffu, s0, o);
            s1 += __shfl_xor_sync(0xffffffffu, s1, o);
        }
        if ((lane & 3) == 0) {
            redsum[r0 * 2 + chh]       = s0;
            redsum[(r0 + 8) * 2 + chh] = s1;
        }
        __syncthreads();
        float rs0 = 1.f / (redsum[r0 * 2] + redsum[r0 * 2 + 1]);
        float rs1 = 1.f / (redsum[(r0 + 8) * 2] + redsum[(r0 + 8) * 2 + 1]);

        uint32_t pf[32];
        #pragma unroll
        for (int t = 0; t < 8; t++) {
            int j = t * 2;
            pf[t * 4 + 0] = h2pack(c[j][0], c[j][1]);
            pf[t * 4 + 1] = h2pack(c[j][2], c[j][3]);
            pf[t * 4 + 2] = h2pack(c[j + 1][0], c[j + 1][1]);
            pf[t * 4 + 3] = h2pack(c[j + 1][2], c[j + 1][3]);
        }

        float o2[8][4];
        #pragma unroll
        for (int nt = 0; nt < 8; nt++)
            #pragma unroll
            for (int e = 0; e < 4; e++) o2[nt][e] = 0.f;

        #pragma unroll
        for (int t = 0; t < 8; t++) {
            #pragma unroll
            for (int dg = 0; dg < 4; dg++) {
                uint32_t t0, t1, t2, t3;
                ldsm4(t0, t1, t2, t3, vb + (dg * 16 + nB) * 528 + (chh * 128 + t * 16 + kB) * 2);
                uint32_t b0v[2] = {t0, t1}, b1v[2] = {t2, t3};
                mma16816(o2[dg * 2],     &pf[t * 4], b0v);
                mma16816(o2[dg * 2 + 1], &pf[t * 4], b1v);
            }
        }

        if (chh == 0) {
            #pragma unroll
            for (int nt = 0; nt < 8; nt++) {
                int d = nt * 8 + (lane & 3) * 2;
                *(float2*)&pairbuf[r0 * 64 + d]       = make_float2(o2[nt][0], o2[nt][1]);
                *(float2*)&pairbuf[(r0 + 8) * 64 + d] = make_float2(o2[nt][2], o2[nt][3]);
            }
        }
        __syncthreads();
        if (chh == 1) {
            #pragma unroll
            for (int nt = 0; nt < 8; nt++) {
                int d = nt * 8 + (lane & 3) * 2;
                float2 pa = *(float2*)&pairbuf[r0 * 64 + d];
                float2 pb = *(float2*)&pairbuf[(r0 + 8) * 64 + d];
                float v0 = (o2[nt][0] + pa.x) * rs0, v1 = (o2[nt][1] + pa.y) * rs0;
                float v2 = (o2[nt][2] + pb.x) * rs1, v3 = (o2[nt][3] + pb.y) * rs1;
                __half* dst = g_att + ((size_t)b * NPIX) * DIMI + h * 64 + d;
                *(uint32_t*)(dst + (size_t)(p0 + r0) * DIMI)     = h2pack(v0, v1);
                *(uint32_t*)(dst + (size_t)(p0 + r0 + 8) * DIMI) = h2pack(v2, v3);
            }
        }
    }
}

// ============================ launch ============================

extern "C" void kernel_launch(void* const* d_in, const int* in_sizes, int n_in,
                              void* d_out, int out_size) {
    const float* fmap       = (const float*)d_in[0];
    const float* context    = (const float*)d_in[1];
    const int*   mask       = (const int*)d_in[2];
    const float* gamma_fmap = (const float*)d_in[3];
    const float* gamma_ctx  = (const float*)d_in[4];
    const float* Wq         = (const float*)d_in[5];
    const float* Wkv        = (const float*)d_in[6];
    const float* Wout       = (const float*)d_in[7];
    float*       out        = (float*)d_out;

    (void)in_sizes; (void)n_in; (void)out_size;

    // Proven-legal resource set: 2 streams + 3 events (R11/R13 footprint).
    static cudaStream_t sA = nullptr, sB = nullptr;
    static cudaEvent_t evRoot = nullptr, evA = nullptr, evB = nullptr;
    if (!sA) {
        cudaStreamCreateWithFlags(&sA, cudaStreamNonBlocking);
        cudaStreamCreateWithFlags(&sB, cudaStreamNonBlocking);
        cudaEventCreateWithFlags(&evRoot, cudaEventDisableTiming);
        cudaEventCreateWithFlags(&evA, cudaEventDisableTiming);
        cudaEventCreateWithFlags(&evB, cudaEventDisableTiming);
    }

    cudaFuncSetAttribute(attn_mma, cudaFuncAttributeMaxDynamicSharedMemorySize, ATTN_SMEM);
    cudaFuncSetAttribute(fuse_fmap, cudaFuncAttributeMaxDynamicSharedMemorySize, FF_SMEM);
    cudaFuncSetAttribute(gemm_qkv, cudaFuncAttributeMaxDynamicSharedMemorySize, GMM_SMEM);
    cudaFuncSetAttribute(gemm_out, cudaFuncAttributeMaxDynamicSharedMemorySize, GMM_SMEM);

    __half *fT, *cx, *at, *wq, *wkv, *wout;
    cudaGetSymbolAddress((void**)&fT, g_fmapT);
    cudaGetSymbolAddress((void**)&cx, g_ctx);
    cudaGetSymbolAddress((void**)&at, g_att);
    cudaGetSymbolAddress((void**)&wq,  g_wq);
    cudaGetSymbolAddress((void**)&wkv, g_wkv);
    cudaGetSymbolAddress((void**)&wout, g_wout);

    // ---- fork preps ----
    cudaEventRecord(evRoot, 0);
    cudaStreamWaitEvent(sA, evRoot, 0);
    cudaStreamWaitEvent(sB, evRoot, 0);

    cvt_all<<<(NWQ + NWKV + NWO + 255) / 256, 256>>>(Wq, Wkv, Wout);
    fuse_fmap<<<dim3(NPIX / 32, 1, B_SZ), 512, FF_SMEM, sA>>>(fmap, gamma_fmap);
    fuse_ctx<<<dim3(1, NCTX, B_SZ), 256, 0, sB>>>(context, gamma_ctx);

    cudaEventRecord(evA, sA);
    cudaEventRecord(evB, sB);
    cudaStreamWaitEvent(0, evA, 0);
    cudaStreamWaitEvent(0, evB, 0);

    // ---- two-group pipelined qkv -> attn -> out (R13 measured-best schedule) ----
    cudaEventRecord(evRoot, 0);          // prep-done marker
    cudaStreamWaitEvent(sB, evRoot, 0);

    gemm_qkv<<<dim3(6, 8, BPG), 256, GMM_SMEM>>>(fT, wq, wkv, cx, 0);
    gemm_qkv<<<dim3(6, 8, BPG), 256, GMM_SMEM, sB>>>(fT, wq, wkv, cx, BPG);

    attn_mma<<<dim3(1, NHEADS, BPG), 256, ATTN_SMEM>>>(mask, 0);
    attn_mma<<<dim3(1, NHEADS, BPG), 256, ATTN_SMEM, sB>>>(mask, BPG);

    gemm_out<<<dim3(NPIX / 128, C_FMAP / 128, BPG), 256, GMM_SMEM>>>(wout, at, out, 0);
    gemm_out<<<dim3(NPIX / 128, C_FMAP / 128, BPG), 256, GMM_SMEM, sB>>>(wout, at, out, BPG);

    cudaEventRecord(evB, sB);            // join group 1
    cudaStreamWaitEvent(0, evB, 0);
}

// round 17
// speedup vs baseline: 1.8744x; 1.0089x over previous
#include <cuda_runtime.h>
#include <cuda_fp16.h>
#include <math.h>
#include <float.h>
#include <stdint.h>

#define B_SZ   32
#define NHEADS 8
#define DHEAD  64
#define C_FMAP 512
#define NPIX   1024
#define NCTX   256
#define CCTX   768
#define DIMI   512   // NHEADS*DHEAD
#define BPG    16    // batches per group (2 groups)

// ============================ scratch globals ============================
__device__ __half g_wq  [DIMI * C_FMAP];
__device__ __half g_wkv [2 * DIMI * CCTX];
__device__ __half g_wout[C_FMAP * DIMI];
__device__ __half g_fmapT[B_SZ * NPIX * C_FMAP];          // [b][p][c]
__device__ __half g_ctx  [B_SZ * NCTX * CCTX];            // [b][n][c]
__device__ __half g_qh [B_SZ * NHEADS * NPIX * DHEAD];    // [b][h][p][d]
__device__ __half g_kh [B_SZ * NHEADS * NCTX * DHEAD];    // [b][h][n][d]
__device__ __half g_vh [B_SZ * NHEADS * DHEAD * NCTX];    // [b][h][d][n]
__device__ __half g_att[B_SZ * NPIX * DIMI];              // [b][p][c]

// ============================ helpers ============================
__device__ __forceinline__ uint32_t smem_u32(const void* p) {
    uint32_t a;
    asm("{ .reg .u64 t; cvta.to.shared.u64 t, %1; cvt.u32.u64 %0, t; }" : "=r"(a) : "l"(p));
    return a;
}
__device__ __forceinline__ void ldsm4(uint32_t& r0, uint32_t& r1, uint32_t& r2, uint32_t& r3,
                                      uint32_t addr) {
    asm volatile("ldmatrix.sync.aligned.m8n8.x4.shared.b16 {%0,%1,%2,%3}, [%4];"
                 : "=r"(r0), "=r"(r1), "=r"(r2), "=r"(r3) : "r"(addr));
}
__device__ __forceinline__ void mma16816(float* c, const uint32_t* a, const uint32_t* b) {
    asm volatile("mma.sync.aligned.m16n8k16.row.col.f32.f16.f16.f32 "
                 "{%0,%1,%2,%3}, {%4,%5,%6,%7}, {%8,%9}, {%0,%1,%2,%3};"
                 : "+f"(c[0]), "+f"(c[1]), "+f"(c[2]), "+f"(c[3])
                 : "r"(a[0]), "r"(a[1]), "r"(a[2]), "r"(a[3]), "r"(b[0]), "r"(b[1]));
}
__device__ __forceinline__ void cpa16(uint32_t dst, const void* src) {
    asm volatile("cp.async.cg.shared.global [%0], [%1], 16;" :: "r"(dst), "l"(src));
}
#define CP_COMMIT() asm volatile("cp.async.commit_group;" ::: "memory")
#define CP_WAIT1()  asm volatile("cp.async.wait_group 1;" ::: "memory")
#define CP_WAIT0()  asm volatile("cp.async.wait_group 0;" ::: "memory")
__device__ __forceinline__ uint32_t h2pack(float lo, float hi) {
    __half2 h = __floats2half2_rn(lo, hi);
    return *(uint32_t*)&h;
}

// ============================ fused norm+prep kernels (per-group) ============================

#define FF_SMEM (512 * 33 * 4 + 16 * 32 * 4 + 32 * 4)
__global__ void __launch_bounds__(512) fuse_fmap(const float* __restrict__ fmap,
                                                 const float* __restrict__ gamma, int b0) {
    extern __shared__ float fs[];
    float* t     = fs;                  // [512][33]
    float* red   = fs + 512 * 33;       // [16][32]
    float* scale = red + 16 * 32;       // [32]
    const int b = b0 + blockIdx.z, p0 = blockIdx.x * 32;
    const int tid = threadIdx.x;

    const float* src = fmap + (size_t)b * C_FMAP * NPIX + p0;
    #pragma unroll
    for (int it = 0; it < 32; it++) {
        int i = it * 512 + tid;
        int c = i >> 5, pi = i & 31;
        t[c * 33 + pi] = src[(size_t)c * NPIX + pi];
    }
    __syncthreads();

    {
        int p = tid & 31, sub = tid >> 5;
        float ss = 0.f;
        #pragma unroll
        for (int j = 0; j < 32; j++) {
            float v = t[(sub + 16 * j) * 33 + p];
            ss += v * v;
        }
        red[sub * 32 + p] = ss;
    }
    __syncthreads();
    if (tid < 32) {
        float ss = 0.f;
        #pragma unroll
        for (int s = 0; s < 16; s++) ss += red[s * 32 + tid];
        scale[tid] = 22.627416997969522f / fmaxf(sqrtf(ss), 1e-12f);
    }
    __syncthreads();

    #pragma unroll
    for (int it = 0; it < 32; it++) {
        int i = it * 512 + tid;
        int p = i >> 9, c = i & 511;
        float v = t[c * 33 + p] * scale[p] * __ldg(&gamma[c]);
        g_fmapT[((size_t)b * NPIX + p0 + p) * C_FMAP + c] = __float2half(v);
    }
}

__global__ void __launch_bounds__(256) fuse_ctx(const float* __restrict__ ctx,
                                                const float* __restrict__ gamma, int b0) {
    __shared__ float wred[8];
    __shared__ float sc;
    const int b = b0 + blockIdx.z, n = blockIdx.y;
    const int tid = threadIdx.x, lane = tid & 31, w = tid >> 5;
    size_t base = ((size_t)b * NCTX + n) * CCTX;
    const float* row = ctx + base;

    float v[3];
    float ss = 0.f;
    #pragma unroll
    for (int j = 0; j < 3; j++) {
        v[j] = row[j * 256 + tid];
        ss += v[j] * v[j];
    }
    #pragma unroll
    for (int o = 16; o; o >>= 1) ss += __shfl_xor_sync(0xffffffffu, ss, o);
    if (lane == 0) wred[w] = ss;
    __syncthreads();
    if (tid == 0) {
        float s = 0.f;
        #pragma unroll
        for (int i = 0; i < 8; i++) s += wred[i];
        sc = 27.712812921102035f / fmaxf(sqrtf(s), 1e-12f);
    }
    __syncthreads();
    float s = sc;
    #pragma unroll
    for (int j = 0; j < 3; j++) {
        int c = j * 256 + tid;
        g_ctx[base + c] = __float2half(v[j] * s * __ldg(&gamma[c]));
    }
}

#define NWQ  (DIMI * C_FMAP)
#define NWKV (2 * DIMI * CCTX)
#define NWO  (C_FMAP * DIMI)
__global__ void cvt_all(const float* __restrict__ wq, const float* __restrict__ wkv,
                        const float* __restrict__ wout) {
    int i = blockIdx.x * blockDim.x + threadIdx.x;
    if (i < NWQ) g_wq[i] = __float2half(wq[i]);
    else if (i < NWQ + NWKV) g_wkv[i - NWQ] = __float2half(wkv[i - NWQ]);
    else if (i < NWQ + NWKV + NWO) g_wout[i - NWQ - NWKV] = __float2half(wout[i - NWQ - NWKV]);
}

// ============================ fp16 mma GEMM body (BK=64, 2-stage, R10 config) ============================
// CTA 128x128, BK=64, 8 warps (4M x 2N) of 32x64, 256 threads, 2 CTAs/SM.

#define APITCH    144
#define HALF_STG  18432              // 128 * 144
#define STG_BYTES (2 * HALF_STG)
#define GMM_SMEM  (2 * STG_BYTES)    // 73728

template <int MODE>
__device__ __forceinline__ void gemm_body(
    const __half* __restrict__ aSrc, const __half* __restrict__ bSrc,
    int K, int m0, int n0, int b, float* __restrict__ outp, char* dsm) {
    const uint32_t smb = smem_u32(dsm);
    const int tid = threadIdx.x, lane = tid & 31, wid = tid >> 5;

    const int wm = (wid >> 1) * 32, wn = (wid & 1) * 64;
    const int rA = (lane & 7) + ((lane >> 3) & 1) * 8;
    const int kA = ((lane >> 4) & 1) * 8;
    const int nB = ((lane >> 4) & 1) * 8 + (lane & 7);
    const int kB = ((lane >> 3) & 1) * 8;

    float c[2][8][4];
    #pragma unroll
    for (int i = 0; i < 2; i++)
        #pragma unroll
        for (int j = 0; j < 8; j++)
            #pragma unroll
            for (int e = 0; e < 4; e++) c[i][j][e] = 0.f;

    const int nk = K >> 6;

    auto load_chunk = [&](int stage, int k0) {
        uint32_t base = smb + stage * STG_BYTES;
        #pragma unroll
        for (int it = 0; it < 4; it++) {
            int i = it * 256 + tid;
            int row = i >> 3, q = i & 7;
            cpa16(base + row * APITCH + q * 16, aSrc + (size_t)(m0 + row) * K + k0 + q * 8);
        }
        #pragma unroll
        for (int it = 0; it < 4; it++) {
            int i = it * 256 + tid;
            int row = i >> 3, q = i & 7;
            cpa16(base + HALF_STG + row * APITCH + q * 16,
                  bSrc + (size_t)(n0 + row) * K + k0 + q * 8);
        }
    };

    load_chunk(0, 0);
    CP_COMMIT();

    for (int ch = 0; ch < nk; ch++) {
        if (ch + 1 < nk) { load_chunk((ch + 1) & 1, (ch + 1) << 6); CP_COMMIT(); CP_WAIT1(); }
        else CP_WAIT0();
        __syncthreads();

        const uint32_t sAb = smb + (ch & 1) * STG_BYTES;
        const uint32_t sBb = sAb + HALF_STG;

        #pragma unroll
        for (int kk = 0; kk < 64; kk += 16) {
            uint32_t af[2][4], bf[8][2];
            #pragma unroll
            for (int mt = 0; mt < 2; mt++)
                ldsm4(af[mt][0], af[mt][1], af[mt][2], af[mt][3],
                      sAb + (wm + mt * 16 + rA) * APITCH + (kk + kA) * 2);
            #pragma unroll
            for (int pr = 0; pr < 4; pr++) {
                uint32_t t0, t1, t2, t3;
                ldsm4(t0, t1, t2, t3, sBb + (wn + pr * 16 + nB) * APITCH + (kk + kB) * 2);
                bf[pr * 2][0] = t0; bf[pr * 2][1] = t1;
                bf[pr * 2 + 1][0] = t2; bf[pr * 2 + 1][1] = t3;
            }
            #pragma unroll
            for (int mt = 0; mt < 2; mt++)
                #pragma unroll
                for (int nt = 0; nt < 8; nt++)
                    mma16816(c[mt][nt], af[mt], bf[nt]);
        }
        __syncthreads();
    }

    // epilogue
    const int gmb = m0 + wm + (lane >> 2);
    const int gnb = n0 + wn + (lane & 3) * 2;
    #pragma unroll
    for (int mt = 0; mt < 2; mt++) {
        #pragma unroll
        for (int nt = 0; nt < 8; nt++) {
            int gm0 = gmb + mt * 16;
            int gn  = gnb + nt * 8;
            float v0 = c[mt][nt][0], v1 = c[mt][nt][1];
            float v2 = c[mt][nt][2], v3 = c[mt][nt][3];
            if (MODE == 0) {
                int h = gn >> 6, d = gn & 63;
                __half* dst = g_qh + ((size_t)(b * NHEADS + h) * NPIX) * DHEAD + d;
                *(uint32_t*)(dst + (size_t)gm0 * DHEAD)       = h2pack(v0, v1);
                *(uint32_t*)(dst + (size_t)(gm0 + 8) * DHEAD) = h2pack(v2, v3);
            } else if (MODE == 1) {
                auto st = [&](int o, float x0, float x1) {
                    if (o < DIMI) {
                        __half* dst = g_kh + ((size_t)(b * NHEADS + (o >> 6)) * NCTX) * DHEAD + (o & 63);
                        dst[(size_t)gn * DHEAD]       = __float2half(x0);
                        dst[(size_t)(gn + 1) * DHEAD] = __float2half(x1);
                    } else {
                        int o2 = o - DIMI;
                        __half* dst = g_vh + ((size_t)(b * NHEADS + (o2 >> 6)) * DHEAD + (o2 & 63)) * NCTX;
                        *(uint32_t*)(dst + gn) = h2pack(x0, x1);
                    }
                };
                st(gm0, v0, v1);
                st(gm0 + 8, v2, v3);
            } else {
                float* dst = outp + ((size_t)b * C_FMAP) * NPIX + gn;
                *(float2*)(dst + (size_t)gm0 * NPIX)       = make_float2(v0, v1);
                *(float2*)(dst + (size_t)(gm0 + 8) * NPIX) = make_float2(v2, v3);
            }
        }
    }
}

// Merged Q + KV projection for one batch group: grid (6, 8, BPG).
__global__ void __launch_bounds__(256, 2)
gemm_qkv(const __half* __restrict__ fT, const __half* __restrict__ wq,
         const __half* __restrict__ wkv, const __half* __restrict__ cx, int b0) {
    extern __shared__ char dsm[];
    const int b = b0 + blockIdx.z;
    if (blockIdx.x < 4) {
        gemm_body<0>(fT + (size_t)b * NPIX * C_FMAP, wq,
                     C_FMAP, blockIdx.y * 128, blockIdx.x * 128, b, nullptr, dsm);
    } else {
        int nx = blockIdx.x - 4;
        gemm_body<1>(wkv, cx + (size_t)b * NCTX * CCTX,
                     CCTX, blockIdx.y * 128, nx * 128, b, nullptr, dsm);
    }
}

__global__ void __launch_bounds__(256, 2)
gemm_out(const __half* __restrict__ wout, const __half* __restrict__ at,
         float* __restrict__ outp, int b0) {
    extern __shared__ char dsm[];
    const int b = b0 + blockIdx.z;
    gemm_body<2>(wout, at + (size_t)b * NPIX * DIMI,
                 DIMI, blockIdx.y * 128, blockIdx.x * 128, b, outp, dsm);
}

// ============================ persistent attention (fp16 mma) ============================

#define AQ_BYTES (64 * 72 * 2)
#define AK_BYTES (256 * 72 * 2)
#define AV_BYTES (64 * 264 * 2)
#define APB_BYTES (64 * 64 * 4)
#define ATTN_SMEM (AQ_BYTES + AK_BYTES + AV_BYTES + APB_BYTES + 1024 + 512 + 512)

__global__ void __launch_bounds__(256, 2) attn_mma(const int* __restrict__ mask, int b0) {
    extern __shared__ char smraw[];
    __half* Qs = (__half*)smraw;
    __half* Ks = (__half*)(smraw + AQ_BYTES);
    __half* Vs = (__half*)(smraw + AQ_BYTES + AK_BYTES);
    float*  pairbuf = (float*)(smraw + AQ_BYTES + AK_BYTES + AV_BYTES);
    float*  mf = pairbuf + 64 * 64;
    float*  redmax = mf + 256;
    float*  redsum = redmax + 128;

    const int tid = threadIdx.x, lane = tid & 31, w = tid >> 5;
    const int rg = w >> 1, chh = w & 1;
    const int b = b0 + blockIdx.z, h = blockIdx.y;

    const uint4* qsrc = (const uint4*)(g_qh + ((size_t)(b * NHEADS + h) * NPIX) * DHEAD);
    const uint4* ksrc = (const uint4*)(g_kh + (size_t)(b * NHEADS + h) * NCTX * DHEAD);
    const uint4* vsrc = (const uint4*)(g_vh + (size_t)(b * NHEADS + h) * DHEAD * NCTX);

    for (int i = tid; i < 2048; i += 256) {
        int row = i >> 3, q = i & 7;
        *(uint4*)&Ks[row * 72 + q * 8] = ksrc[i];
    }
    for (int i = tid; i < 2048; i += 256) {
        int row = i >> 5, q = i & 31;
        *(uint4*)&Vs[row * 264 + q * 8] = vsrc[i];
    }
    mf[tid] = (mask[b * NCTX + tid] != 0) ? 1.0f : 0.0f;

    const uint32_t qb = smem_u32(Qs), kb = smem_u32(Ks), vb = smem_u32(Vs);
    const int rA = (lane & 7) + ((lane >> 3) & 1) * 8;
    const int kA = ((lane >> 4) & 1) * 8;
    const int nB = ((lane >> 4) & 1) * 8 + (lane & 7);
    const int kB = ((lane >> 3) & 1) * 8;
    const int r0 = rg * 16 + (lane >> 2);

    for (int pt = 0; pt < 16; pt++) {
        const int p0 = pt * 64;
        __syncthreads();
        for (int i = tid; i < 512; i += 256) {
            int row = i >> 3, q = i & 7;
            *(uint4*)&Qs[row * 72 + q * 8] = qsrc[pt * 512 + i];
        }
        __syncthreads();

        float c[16][4];
        #pragma unroll
        for (int j = 0; j < 16; j++)
            #pragma unroll
            for (int e = 0; e < 4; e++) c[j][e] = 0.f;

        #pragma unroll
        for (int kst = 0; kst < 4; kst++) {
            int kk = kst * 16;
            uint32_t a[4];
            ldsm4(a[0], a[1], a[2], a[3], qb + (rg * 16 + rA) * 144 + (kk + kA) * 2);
            #pragma unroll
            for (int g16 = 0; g16 < 8; g16++) {
                uint32_t t0, t1, t2, t3;
                ldsm4(t0, t1, t2, t3, kb + (chh * 128 + g16 * 16 + nB) * 144 + (kk + kB) * 2);
                uint32_t b0v[2] = {t0, t1}, b1v[2] = {t2, t3};
                mma16816(c[g16 * 2],     a, b0v);
                mma16816(c[g16 * 2 + 1], a, b1v);
            }
        }

        float m0 = -FLT_MAX, m1 = -FLT_MAX;
        #pragma unroll
        for (int j = 0; j < 16; j++) {
            c[j][0] *= 0.125f; c[j][1] *= 0.125f; c[j][2] *= 0.125f; c[j][3] *= 0.125f;
            m0 = fmaxf(m0, fmaxf(c[j][0], c[j][1]));
            m1 = fmaxf(m1, fmaxf(c[j][2], c[j][3]));
        }
        #pragma unroll
        for (int o = 1; o <= 2; o <<= 1) {
            m0 = fmaxf(m0, __shfl_xor_sync(0xffffffffu, m0, o));
            m1 = fmaxf(m1, __shfl_xor_sync(0xffffffffu, m1, o));
        }
        if ((lane & 3) == 0) {
            redmax[r0 * 2 + chh]       = m0;
            redmax[(r0 + 8) * 2 + chh] = m1;
        }
        __syncthreads();
        float M0 = fmaxf(redmax[r0 * 2], redmax[r0 * 2 + 1]);
        float M1 = fmaxf(redmax[(r0 + 8) * 2], redmax[(r0 + 8) * 2 + 1]);

        float s0 = 0.f, s1 = 0.f;
        #pragma unroll
        for (int j = 0; j < 16; j++) {
            int col = chh * 128 + j * 8 + (lane & 3) * 2;
            float mA = mf[col], mB = mf[col + 1];
            float e0 = __expf(c[j][0] - M0) * mA;
            float e1 = __expf(c[j][1] - M0) * mB;
            float e2 = __expf(c[j][2] - M1) * mA;
            float e3 = __expf(c[j][3] - M1) * mB;
            c[j][0] = e0; c[j][1] = e1; c[j][2] = e2; c[j][3] = e3;
            s0 += e0 + e1; s1 += e2 + e3;
        }
        #pragma unroll
        for (int o = 1; o <= 2; o <<= 1) {
            s0 += __shfl_xor_sync(0xffffffffu, s0, o);
            s1 += __shfl_xor_sync(0xffffffffu, s1, o);
        }
        if ((lane & 3) == 0) {
            redsum[r0 * 2 + chh]       = s0;
            redsum[(r0 + 8) * 2 + chh] = s1;
        }
        __syncthreads();
        float rs0 = 1.f / (redsum[r0 * 2] + redsum[r0 * 2 + 1]);
        float rs1 = 1.f / (redsum[(r0 + 8) * 2] + redsum[(r0 + 8) * 2 + 1]);

        uint32_t pf[32];
        #pragma unroll
        for (int t = 0; t < 8; t++) {
            int j = t * 2;
            pf[t * 4 + 0] = h2pack(c[j][0], c[j][1]);
            pf[t * 4 + 1] = h2pack(c[j][2], c[j][3]);
            pf[t * 4 + 2] = h2pack(c[j + 1][0], c[j + 1][1]);
            pf[t * 4 + 3] = h2pack(c[j + 1][2], c[j + 1][3]);
        }

        float o2[8][4];
        #pragma unroll
        for (int nt = 0; nt < 8; nt++)
            #pragma unroll
            for (int e = 0; e < 4; e++) o2[nt][e] = 0.f;

        #pragma unroll
        for (int t = 0; t < 8; t++) {
            #pragma unroll
            for (int dg = 0; dg < 4; dg++) {
                uint32_t t0, t1, t2, t3;
                ldsm4(t0, t1, t2, t3, vb + (dg * 16 + nB) * 528 + (chh * 128 + t * 16 + kB) * 2);
                uint32_t b0v[2] = {t0, t1}, b1v[2] = {t2, t3};
                mma16816(o2[dg * 2],     &pf[t * 4], b0v);
                mma16816(o2[dg * 2 + 1], &pf[t * 4], b1v);
            }
        }

        if (chh == 0) {
            #pragma unroll
            for (int nt = 0; nt < 8; nt++) {
                int d = nt * 8 + (lane & 3) * 2;
                *(float2*)&pairbuf[r0 * 64 + d]       = make_float2(o2[nt][0], o2[nt][1]);
                *(float2*)&pairbuf[(r0 + 8) * 64 + d] = make_float2(o2[nt][2], o2[nt][3]);
            }
        }
        __syncthreads();
        if (chh == 1) {
            #pragma unroll
            for (int nt = 0; nt < 8; nt++) {
                int d = nt * 8 + (lane & 3) * 2;
                float2 pa = *(float2*)&pairbuf[r0 * 64 + d];
                float2 pb = *(float2*)&pairbuf[(r0 + 8) * 64 + d];
                float v0 = (o2[nt][0] + pa.x) * rs0, v1 = (o2[nt][1] + pa.y) * rs0;
                float v2 = (o2[nt][2] + pb.x) * rs1, v3 = (o2[nt][3] + pb.y) * rs1;
                __half* dst = g_att + ((size_t)b * NPIX) * DIMI + h * 64 + d;
                *(uint32_t*)(dst + (size_t)(p0 + r0) * DIMI)     = h2pack(v0, v1);
                *(uint32_t*)(dst + (size_t)(p0 + r0 + 8) * DIMI) = h2pack(v2, v3);
            }
        }
    }
}

// ============================ launch ============================

extern "C" void kernel_launch(void* const* d_in, const int* in_sizes, int n_in,
                              void* d_out, int out_size) {
    const float* fmap       = (const float*)d_in[0];
    const float* context    = (const float*)d_in[1];
    const int*   mask       = (const int*)d_in[2];
    const float* gamma_fmap = (const float*)d_in[3];
    const float* gamma_ctx  = (const float*)d_in[4];
    const float* Wq         = (const float*)d_in[5];
    const float* Wkv        = (const float*)d_in[6];
    const float* Wout       = (const float*)d_in[7];
    float*       out        = (float*)d_out;

    (void)in_sizes; (void)n_in; (void)out_size;

    // Proven-legal resource set: 2 streams + 3 events.
    static cudaStream_t sA = nullptr, sB = nullptr;
    static cudaEvent_t evRoot = nullptr, evA = nullptr, evB = nullptr;
    if (!sA) {
        cudaStreamCreateWithFlags(&sA, cudaStreamNonBlocking);
        cudaStreamCreateWithFlags(&sB, cudaStreamNonBlocking);
        cudaEventCreateWithFlags(&evRoot, cudaEventDisableTiming);
        cudaEventCreateWithFlags(&evA, cudaEventDisableTiming);
        cudaEventCreateWithFlags(&evB, cudaEventDisableTiming);
    }

    cudaFuncSetAttribute(attn_mma, cudaFuncAttributeMaxDynamicSharedMemorySize, ATTN_SMEM);
    cudaFuncSetAttribute(fuse_fmap, cudaFuncAttributeMaxDynamicSharedMemorySize, FF_SMEM);
    cudaFuncSetAttribute(gemm_qkv, cudaFuncAttributeMaxDynamicSharedMemorySize, GMM_SMEM);
    cudaFuncSetAttribute(gemm_out, cudaFuncAttributeMaxDynamicSharedMemorySize, GMM_SMEM);

    __half *fT, *cx, *at, *wq, *wkv, *wout;
    cudaGetSymbolAddress((void**)&fT, g_fmapT);
    cudaGetSymbolAddress((void**)&cx, g_ctx);
    cudaGetSymbolAddress((void**)&at, g_att);
    cudaGetSymbolAddress((void**)&wq,  g_wq);
    cudaGetSymbolAddress((void**)&wkv, g_wkv);
    cudaGetSymbolAddress((void**)&wout, g_wout);

    // ---- fork: cvt on sA; group-0 preps on default; group-1 preps on sB ----
    cudaEventRecord(evRoot, 0);
    cudaStreamWaitEvent(sA, evRoot, 0);
    cudaStreamWaitEvent(sB, evRoot, 0);

    cvt_all<<<(NWQ + NWKV + NWO + 255) / 256, 256, 0, sA>>>(Wq, Wkv, Wout);
    cudaEventRecord(evA, sA);           // weights ready

    fuse_fmap<<<dim3(NPIX / 32, 1, BPG), 512, FF_SMEM>>>(fmap, gamma_fmap, 0);
    fuse_ctx<<<dim3(1, NCTX, BPG), 256>>>(context, gamma_ctx, 0);

    fuse_fmap<<<dim3(NPIX / 32, 1, BPG), 512, FF_SMEM, sB>>>(fmap, gamma_fmap, BPG);
    fuse_ctx<<<dim3(1, NCTX, BPG), 256, 0, sB>>>(context, gamma_ctx, BPG);

    // each chain waits only on its own preps (stream order) + weights (evA)
    cudaStreamWaitEvent(0, evA, 0);
    cudaStreamWaitEvent(sB, evA, 0);

    // ---- two-group pipelined qkv -> attn -> out (R13 measured-best schedule) ----
    gemm_qkv<<<dim3(6, 8, BPG), 256, GMM_SMEM>>>(fT, wq, wkv, cx, 0);
    gemm_qkv<<<dim3(6, 8, BPG), 256, GMM_SMEM, sB>>>(fT, wq, wkv, cx, BPG);

    attn_mma<<<dim3(1, NHEADS, BPG), 256, ATTN_SMEM>>>(mask, 0);
    attn_mma<<<dim3(1, NHEADS, BPG), 256, ATTN_SMEM, sB>>>(mask, BPG);

    gemm_out<<<dim3(NPIX / 128, C_FMAP / 128, BPG), 256, GMM_SMEM>>>(wout, at, out, 0);
    gemm_out<<<dim3(NPIX / 128, C_FMAP / 128, BPG), 256, GMM_SMEM, sB>>>(wout, at, out, BPG);

    cudaEventRecord(evB, sB);            // join group 1
    cudaStreamWaitEvent(0, evB, 0);
}